// round 7
// baseline (speedup 1.0000x reference)
#include <cuda_runtime.h>
#include <cuda_bf16.h>
#include <cuda_fp16.h>
#include <mma.h>
#include <math.h>
#include <stdint.h>

using namespace nvcuda;

#define D 128
#define MAXN 50432
#define MAXE 1700000

// ---------------- scratch (device globals: allocation-free) ----------------
__device__ float g_dinv[MAXN];                 // deg -> rsqrt(deg)
__device__ int   g_cnt[MAXN];                  // in-degree histogram
__device__ int   g_off[MAXN + 1];              // CSR offsets
__device__ int   g_cur[MAXN];                  // placement cursors
__device__ int   g_tmp[MAXN];                  // scan scratch
__device__ int   g_part[64];                   // scan block partials
__device__ int2  g_srt[MAXE];                  // packed (row, norm) per edge, grouped by col
__device__ __half g_xhh[(size_t)MAXN * 256];   // [x|h] fp16 gather source
__device__ __half g_rhh[(size_t)MAXN * D];     // r*h fp16 gather source
__device__ float g_sxh[(size_t)MAXN * 256];    // [S@xin | S@h]   (GEMM1 A, fp32)
__device__ float g_P[(size_t)MAXN * D];        // xh_pre + bias (compact)
__device__ float g_Sr[(size_t)MAXN * D];       // S @ (r*h)      (GEMM2 A, fp32)
__device__ float g_z[(size_t)MAXN * D];        // z gate
__device__ float g_bias[384];                  // [bxz+bhz | bxr+bhr | bxh+bhh]
__device__ __nv_bfloat16 g_Wt1hi[384 * 256];   // GEMM1 B (n-major, split)
__device__ __nv_bfloat16 g_Wt1lo[384 * 256];
__device__ __nv_bfloat16 g_Wt2hi[128 * 128];   // GEMM2 B (n-major, split)
__device__ __nv_bfloat16 g_Wt2lo[128 * 128];

__device__ __forceinline__ float sigmoidf(float x) { return 1.0f / (1.0f + expf(-x)); }

// ---------------- degree / histogram ----------------
__global__ void k_deg_init(int n) {
    int i = blockIdx.x * blockDim.x + threadIdx.x;
    if (i < n) { g_dinv[i] = 1.0f; g_cnt[i] = 0; }
}
__global__ void k_deg_edges(const int* __restrict__ coli, const float* __restrict__ w, int E) {
    int e = blockIdx.x * blockDim.x + threadIdx.x;
    if (e < E) {
        int c = coli[e];
        atomicAdd(&g_dinv[c], w[e]);
        atomicAdd(&g_cnt[c], 1);
    }
}
__global__ void k_dinv(int n) {
    int i = blockIdx.x * blockDim.x + threadIdx.x;
    if (i < n) {
        float d = g_dinv[i];
        g_dinv[i] = (d > 0.0f) ? rsqrtf(d) : 0.0f;
    }
}

// ---------------- multi-block scan ----------------
__global__ void __launch_bounds__(1024)
k_scan1(int n) {
    __shared__ int warpsum[32];
    int i = blockIdx.x * 1024 + threadIdx.x;
    int lane = threadIdx.x & 31, wid = threadIdx.x >> 5;
    int v = (i < n) ? g_cnt[i] : 0;
    int x = v;
#pragma unroll
    for (int o = 1; o < 32; o <<= 1) {
        int t = __shfl_up_sync(~0u, x, o);
        if (lane >= o) x += t;
    }
    if (lane == 31) warpsum[wid] = x;
    __syncthreads();
    if (wid == 0) {
        int s = warpsum[lane];
#pragma unroll
        for (int o = 1; o < 32; o <<= 1) {
            int t = __shfl_up_sync(~0u, s, o);
            if (lane >= o) s += t;
        }
        warpsum[lane] = s;
    }
    __syncthreads();
    int incl = x + ((wid > 0) ? warpsum[wid - 1] : 0);
    if (i < n) g_tmp[i] = incl;
    if (threadIdx.x == 1023) g_part[blockIdx.x] = incl;
}
__global__ void k_scan2(int nb) {
    __shared__ int sm[64];
    int t = threadIdx.x;
    sm[t] = (t < nb) ? g_part[t] : 0;
    __syncthreads();
    for (int o = 1; o < 64; o <<= 1) {
        int v = (t >= o) ? sm[t - o] : 0;
        __syncthreads();
        sm[t] += v;
        __syncthreads();
    }
    g_part[t] = (t > 0) ? sm[t - 1] : 0;
}
__global__ void k_scan3(int n) {
    int i = blockIdx.x * blockDim.x + threadIdx.x;
    if (i >= n) return;
    int off = g_tmp[i] + g_part[i >> 10];
    g_off[i + 1] = off;
    g_cur[i] = off - g_cnt[i];
    if (i == 0) g_off[0] = 0;
}

// ---------------- placement scatter ----------------
__global__ void k_place(const int* __restrict__ rowi, const int* __restrict__ coli,
                        const float* __restrict__ w, int E) {
    int e = blockIdx.x * blockDim.x + threadIdx.x;
    if (e >= E) return;
    int r = rowi[e], c = coli[e];
    float nrm = w[e] * __ldg(g_dinv + r) * __ldg(g_dinv + c);
    int pos = atomicAdd(&g_cur[c], 1);
    g_srt[pos] = make_int2(r, __float_as_int(nrm));
}

// ---------------- weight build (transposed + bf16 split) + combined bias ----------------
__global__ void k_build_wt1(const float* __restrict__ Wxz, const float* __restrict__ Whz,
                            const float* __restrict__ Wxr, const float* __restrict__ Whr,
                            const float* __restrict__ Wxh,
                            const float* __restrict__ bxz, const float* __restrict__ bhz,
                            const float* __restrict__ bxr, const float* __restrict__ bhr,
                            const float* __restrict__ bxh, const float* __restrict__ bhh) {
    int idx = blockIdx.x * blockDim.x + threadIdx.x;
    if (idx >= 384 * 256) return;
    if (idx < 384) {
        int blk = idx >> 7, j = idx & 127;
        float b;
        if (blk == 0)      b = bxz[j] + bhz[j];
        else if (blk == 1) b = bxr[j] + bhr[j];
        else               b = bxh[j] + bhh[j];
        g_bias[idx] = b;
    }
    int n = idx / 256, k = idx % 256;
    int blk = n >> 7, nn = n & 127;
    float v;
    if (blk == 0)      v = (k < 128) ? Wxz[k * 128 + nn] : Whz[(k - 128) * 128 + nn];
    else if (blk == 1) v = (k < 128) ? Wxr[k * 128 + nn] : Whr[(k - 128) * 128 + nn];
    else               v = (k < 128) ? Wxh[k * 128 + nn] : 0.0f;
    __nv_bfloat16 hi = __float2bfloat16(v);
    g_Wt1hi[idx] = hi;
    g_Wt1lo[idx] = __float2bfloat16(v - __bfloat162float(hi));
}
__global__ void k_build_wt2(const float* __restrict__ Whh) {
    int idx = blockIdx.x * blockDim.x + threadIdx.x;
    if (idx >= 128 * 128) return;
    int n = idx / 128, k = idx % 128;
    float v = Whh[k * 128 + n];
    __nv_bfloat16 hi = __float2bfloat16(v);
    g_Wt2hi[idx] = hi;
    g_Wt2lo[idx] = __float2bfloat16(v - __bfloat162float(hi));
}

// ---------------- prep: pack [x|h] fp32 -> fp16 gather rows (layer 0 only) ----------------
__global__ void k_prep(const float* __restrict__ x, const float* __restrict__ h, int n) {
    int idx = blockIdx.x * blockDim.x + threadIdx.x;
    if (idx >= n * 32) return;
    int m = idx >> 5, j = idx & 31;
    const float4* src = (j < 16) ? (const float4*)x + (size_t)m * 32 + 2 * j
                                 : (const float4*)h + (size_t)m * 32 + 2 * (j - 16);
    float4 a = __ldg(src), b = __ldg(src + 1);
    __half2 h0 = __floats2half2_rn(a.x, a.y), h1 = __floats2half2_rn(a.z, a.w);
    __half2 h2 = __floats2half2_rn(b.x, b.y), h3 = __floats2half2_rn(b.z, b.w);
    uint4 o;
    o.x = *(uint32_t*)&h0; o.y = *(uint32_t*)&h1; o.z = *(uint32_t*)&h2; o.w = *(uint32_t*)&h3;
    ((uint4*)g_xhh)[(size_t)m * 32 + j] = o;
}

// ---------------- CSR gather: 256-wide fp16 -> g_sxh fp32, warp per node ----------------
__global__ void __launch_bounds__(256)
k_csr256(int n) {
    int node = (blockIdx.x * blockDim.x + threadIdx.x) >> 5;
    if (node >= n) return;
    int lane = threadIdx.x & 31;
    const uint4* src = (const uint4*)g_xhh;
    float di = __ldg(g_dinv + node);
    float s = di * di;
    float acc[8];
    {
        uint4 v = __ldg(src + (size_t)node * 32 + lane);
        float2 f0 = __half22float2(*(__half2*)&v.x), f1 = __half22float2(*(__half2*)&v.y);
        float2 f2 = __half22float2(*(__half2*)&v.z), f3 = __half22float2(*(__half2*)&v.w);
        acc[0] = s * f0.x; acc[1] = s * f0.y; acc[2] = s * f1.x; acc[3] = s * f1.y;
        acc[4] = s * f2.x; acc[5] = s * f2.y; acc[6] = s * f3.x; acc[7] = s * f3.y;
    }
    int e0 = __ldg(g_off + node), e1 = __ldg(g_off + node + 1);
#pragma unroll 4
    for (int e = e0; e < e1; e++) {
        int2 p = __ldg(g_srt + e);
        float nrm = __int_as_float(p.y);
        uint4 v = __ldg(src + (size_t)p.x * 32 + lane);
        float2 f0 = __half22float2(*(__half2*)&v.x), f1 = __half22float2(*(__half2*)&v.y);
        float2 f2 = __half22float2(*(__half2*)&v.z), f3 = __half22float2(*(__half2*)&v.w);
        acc[0] += nrm * f0.x; acc[1] += nrm * f0.y; acc[2] += nrm * f1.x; acc[3] += nrm * f1.y;
        acc[4] += nrm * f2.x; acc[5] += nrm * f2.y; acc[6] += nrm * f3.x; acc[7] += nrm * f3.y;
    }
    float4* dst = (float4*)g_sxh + (size_t)node * 64 + 2 * lane;
    dst[0] = make_float4(acc[0], acc[1], acc[2], acc[3]);
    dst[1] = make_float4(acc[4], acc[5], acc[6], acc[7]);
}

// ---------------- CSR gather: 128-wide fp16 (g_rhh -> g_Sr), warp per node ----------------
__global__ void __launch_bounds__(256)
k_csr128(int n) {
    int node = (blockIdx.x * blockDim.x + threadIdx.x) >> 5;
    if (node >= n) return;
    int lane = threadIdx.x & 31;
    const uint2* src = (const uint2*)g_rhh;
    float di = __ldg(g_dinv + node);
    float s = di * di;
    float acc[4];
    {
        uint2 v = __ldg(src + (size_t)node * 32 + lane);
        float2 f0 = __half22float2(*(__half2*)&v.x), f1 = __half22float2(*(__half2*)&v.y);
        acc[0] = s * f0.x; acc[1] = s * f0.y; acc[2] = s * f1.x; acc[3] = s * f1.y;
    }
    int e0 = __ldg(g_off + node), e1 = __ldg(g_off + node + 1);
#pragma unroll 4
    for (int e = e0; e < e1; e++) {
        int2 p = __ldg(g_srt + e);
        float nrm = __int_as_float(p.y);
        uint2 v = __ldg(src + (size_t)p.x * 32 + lane);
        float2 f0 = __half22float2(*(__half2*)&v.x), f1 = __half22float2(*(__half2*)&v.y);
        acc[0] += nrm * f0.x; acc[1] += nrm * f0.y; acc[2] += nrm * f1.x; acc[3] += nrm * f1.y;
    }
    ((float4*)g_Sr)[(size_t)node * 32 + lane] = make_float4(acc[0], acc[1], acc[2], acc[3]);
}

// ---------------- WMMA split-bf16 GEMM with fused elementwise epilogue ----------------
// mode 1 (GEMM1, ntiles=6): tiles [0,1]->z=sigmoid(+bias)->g_z; [2,3]->r=sigmoid(+bias),
//   rh=r*h->g_rhh (fp16); [4,5]->g_P = acc + bias.
// mode 2 (GEMM2, ntiles=2): ht=tanh(g_P+acc); ho=z*h+(1-z)*ht -> out;
//   if hnext != null also writes next-layer g_xhh = [half(ho)|half(hnext)].
__global__ void __launch_bounds__(256, 1)
k_wgemm(const float* __restrict__ A, const __nv_bfloat16* __restrict__ Bhi,
        const __nv_bfloat16* __restrict__ Blo,
        int M, int K, int ntiles, int mode,
        const float* __restrict__ hrow, const float* __restrict__ hnext,
        float* __restrict__ out) {
    extern __shared__ char smem[];
    const int tid = threadIdx.x;
    const int blockRow = blockIdx.x * 128;
    const int ldS = K + 16;

    __nv_bfloat16* Ahi = (__nv_bfloat16*)smem;
    __nv_bfloat16* Alo = Ahi + 128 * ldS;
    __nv_bfloat16* Bh  = Alo + 128 * ldS;
    __nv_bfloat16* Bl  = Bh + 64 * ldS;
    float* stage = (float*)Bh;                 // 128 x 68 fp32 staging (reuses B region)
    const int ldSt = 68;

    // ---- load A fp32 -> split bf16 hi/lo into SMEM (once) ----
    {
        const int K4 = K >> 2;
        for (int idx = tid; idx < 128 * K4; idx += 256) {
            int r = idx / K4, c = (idx % K4) * 4;
            float4 v = __ldg((const float4*)(A + (size_t)(blockRow + r) * K + c));
            __nv_bfloat16 h0 = __float2bfloat16(v.x), h1 = __float2bfloat16(v.y);
            __nv_bfloat16 h2 = __float2bfloat16(v.z), h3 = __float2bfloat16(v.w);
            __nv_bfloat16 l0 = __float2bfloat16(v.x - __bfloat162float(h0));
            __nv_bfloat16 l1 = __float2bfloat16(v.y - __bfloat162float(h1));
            __nv_bfloat16 l2 = __float2bfloat16(v.z - __bfloat162float(h2));
            __nv_bfloat16 l3 = __float2bfloat16(v.w - __bfloat162float(h3));
            uint32_t hw0 = ((uint32_t)__bfloat16_as_ushort(h1) << 16) | __bfloat16_as_ushort(h0);
            uint32_t hw1 = ((uint32_t)__bfloat16_as_ushort(h3) << 16) | __bfloat16_as_ushort(h2);
            uint32_t lw0 = ((uint32_t)__bfloat16_as_ushort(l1) << 16) | __bfloat16_as_ushort(l0);
            uint32_t lw1 = ((uint32_t)__bfloat16_as_ushort(l3) << 16) | __bfloat16_as_ushort(l2);
            *(uint2*)(Ahi + (size_t)r * ldS + c) = make_uint2(hw0, hw1);
            *(uint2*)(Alo + (size_t)r * ldS + c) = make_uint2(lw0, lw1);
        }
    }

    const int warpId = tid >> 5;
    const int wm = warpId & 3;
    const int wn = warpId >> 2;
    const int row0 = wm * 32;
    const int col0 = wn * 32;
    const int K8 = K >> 3;

    for (int nt = 0; nt < ntiles; nt++) {
        const int n0 = nt * 64;
        __syncthreads();  // staging / previous epilogue done; B region reusable
        for (int idx = tid; idx < 64 * K8; idx += 256) {
            int n = idx / K8, c = (idx % K8) * 8;
            uint4 vh = __ldg((const uint4*)(Bhi + (size_t)(n0 + n) * K + c));
            uint4 vl = __ldg((const uint4*)(Blo + (size_t)(n0 + n) * K + c));
            *(uint4*)(Bh + (size_t)n * ldS + c) = vh;
            *(uint4*)(Bl + (size_t)n * ldS + c) = vl;
        }
        __syncthreads();

        wmma::fragment<wmma::accumulator, 16, 16, 16, float> acc[2][2];
#pragma unroll
        for (int i = 0; i < 2; i++)
#pragma unroll
            for (int j = 0; j < 2; j++) wmma::fill_fragment(acc[i][j], 0.0f);

        for (int k0 = 0; k0 < K; k0 += 16) {
            wmma::fragment<wmma::matrix_a, 16, 16, 16, __nv_bfloat16, wmma::row_major> ah[2], al[2];
            wmma::fragment<wmma::matrix_b, 16, 16, 16, __nv_bfloat16, wmma::col_major> bh[2], bl[2];
#pragma unroll
            for (int i = 0; i < 2; i++) {
                wmma::load_matrix_sync(ah[i], Ahi + (size_t)(row0 + i * 16) * ldS + k0, ldS);
                wmma::load_matrix_sync(al[i], Alo + (size_t)(row0 + i * 16) * ldS + k0, ldS);
            }
#pragma unroll
            for (int j = 0; j < 2; j++) {
                wmma::load_matrix_sync(bh[j], Bh + (size_t)(col0 + j * 16) * ldS + k0, ldS);
                wmma::load_matrix_sync(bl[j], Bl + (size_t)(col0 + j * 16) * ldS + k0, ldS);
            }
#pragma unroll
            for (int i = 0; i < 2; i++)
#pragma unroll
                for (int j = 0; j < 2; j++) {
                    wmma::mma_sync(acc[i][j], ah[i], bh[j], acc[i][j]);
                    wmma::mma_sync(acc[i][j], ah[i], bl[j], acc[i][j]);
                    wmma::mma_sync(acc[i][j], al[i], bh[j], acc[i][j]);
                }
        }
        __syncthreads();  // all warps done reading Bh/Bl -> safe to overwrite with staging

#pragma unroll
        for (int i = 0; i < 2; i++)
#pragma unroll
            for (int j = 0; j < 2; j++)
                wmma::store_matrix_sync(stage + (size_t)(row0 + i * 16) * ldSt + col0 + j * 16,
                                        acc[i][j], ldSt, wmma::mem_row_major);
        __syncthreads();

        // ---- fused elementwise epilogue on the 128x64 staged tile ----
        for (int g = tid; g < 128 * 32; g += 256) {
            int r = g >> 5, cp = (g & 31) * 2;     // row, col-pair within tile
            int m = blockRow + r;
            if (m >= M) continue;
            float2 v = *(float2*)(stage + (size_t)r * ldSt + cp);
            if (mode == 1) {
                int blk = n0 >> 7;
                int jj = (n0 & 127) + cp;          // column within 128-wide D
                if (blk == 0) {
                    float2 zv;
                    zv.x = sigmoidf(v.x + g_bias[jj]);
                    zv.y = sigmoidf(v.y + g_bias[jj + 1]);
                    *(float2*)(g_z + (size_t)m * D + jj) = zv;
                } else if (blk == 1) {
                    float2 hv = *(const float2*)(hrow + (size_t)m * D + jj);
                    float r0 = sigmoidf(v.x + g_bias[128 + jj]);
                    float r1 = sigmoidf(v.y + g_bias[128 + jj + 1]);
                    __half2 rh = __floats2half2_rn(r0 * hv.x, r1 * hv.y);
                    *(uint32_t*)(g_rhh + (size_t)m * D + jj) = *(uint32_t*)&rh;
                } else {
                    float2 pv;
                    pv.x = v.x + g_bias[256 + jj];
                    pv.y = v.y + g_bias[256 + jj + 1];
                    *(float2*)(g_P + (size_t)m * D + jj) = pv;
                }
            } else {
                int jj = n0 + cp;
                float2 pv = *(const float2*)(g_P + (size_t)m * D + jj);
                float2 zv = *(const float2*)(g_z + (size_t)m * D + jj);
                float2 hv = *(const float2*)(hrow + (size_t)m * D + jj);
                float ht0 = tanhf(pv.x + v.x), ht1 = tanhf(pv.y + v.y);
                float2 ho;
                ho.x = zv.x * hv.x + (1.0f - zv.x) * ht0;
                ho.y = zv.y * hv.y + (1.0f - zv.y) * ht1;
                *(float2*)(out + (size_t)m * D + jj) = ho;
                if (hnext) {
                    __half2 hx = __floats2half2_rn(ho.x, ho.y);
                    *(uint32_t*)(g_xhh + (size_t)m * 256 + jj) = *(uint32_t*)&hx;
                    float2 hn = *(const float2*)(hnext + (size_t)m * D + jj);
                    __half2 hh = __floats2half2_rn(hn.x, hn.y);
                    *(uint32_t*)(g_xhh + (size_t)m * 256 + 128 + jj) = *(uint32_t*)&hh;
                }
            }
        }
    }
}

// ---------------- host ----------------
extern "C" void kernel_launch(void* const* d_in, const int* in_sizes, int n_in,
                              void* d_out, int out_size) {
    const float* x   = (const float*)d_in[0];
    const int*   ei  = (const int*)d_in[1];
    const float* ew  = (const float*)d_in[2];
    const float* h   = (const float*)d_in[3];
    const float* Wxz = (const float*)d_in[4];  const float* bxz = (const float*)d_in[5];
    const float* Whz = (const float*)d_in[6];  const float* bhz = (const float*)d_in[7];
    const float* Wxr = (const float*)d_in[8];  const float* bxr = (const float*)d_in[9];
    const float* Whr = (const float*)d_in[10]; const float* bhr = (const float*)d_in[11];
    const float* Wxh = (const float*)d_in[12]; const float* bxh = (const float*)d_in[13];
    const float* Whh = (const float*)d_in[14]; const float* bhh = (const float*)d_in[15];
    float* out = (float*)d_out;

    int N = in_sizes[0] / D;
    int E = in_sizes[2];
    int L = in_sizes[5] / D;

    const int* rowi = ei;
    const int* coli = ei + E;

    float *p_sxh, *p_Sr;
    __nv_bfloat16 *p_w1h, *p_w1l, *p_w2h, *p_w2l;
    cudaGetSymbolAddress((void**)&p_sxh, g_sxh);
    cudaGetSymbolAddress((void**)&p_Sr,  g_Sr);
    cudaGetSymbolAddress((void**)&p_w1h, g_Wt1hi);
    cudaGetSymbolAddress((void**)&p_w1l, g_Wt1lo);
    cudaGetSymbolAddress((void**)&p_w2h, g_Wt2hi);
    cudaGetSymbolAddress((void**)&p_w2l, g_Wt2lo);

    int smem1 = 2 * (128 + 64) * (256 + 16) * 2;  // K=256
    int smem2 = 2 * (128 + 64) * (128 + 16) * 2;  // K=128
    cudaFuncSetAttribute(k_wgemm, cudaFuncAttributeMaxDynamicSharedMemorySize, smem1);

    // ---- one-time: degrees, CSR build ----
    k_deg_init<<<(N + 255) / 256, 256>>>(N);
    k_deg_edges<<<(E + 255) / 256, 256>>>(coli, ew, E);
    k_dinv<<<(N + 255) / 256, 256>>>(N);
    int nscan = (N + 1023) / 1024;
    k_scan1<<<nscan, 1024>>>(N);
    k_scan2<<<1, 64>>>(nscan);
    k_scan3<<<(N + 255) / 256, 256>>>(N);
    k_place<<<(E + 255) / 256, 256>>>(rowi, coli, ew, E);

    int nwblocks = (N * 32 + 255) / 256;  // warp per node
    int mtiles = (N + 127) / 128;

    k_prep<<<(N * 32 + 255) / 256, 256>>>(x, h, N);  // layer 0 pack

    for (int i = 0; i < L; i++) {
        const float* hi = h + (size_t)i * N * D;
        const float* hnext = (i + 1 < L) ? h + (size_t)(i + 1) * N * D : nullptr;
        float* oi = out + (size_t)i * N * D;

        k_build_wt1<<<(384 * 256 + 255) / 256, 256>>>(
            Wxz + (size_t)i * D * D, Whz + (size_t)i * D * D,
            Wxr + (size_t)i * D * D, Whr + (size_t)i * D * D, Wxh + (size_t)i * D * D,
            bxz + i * D, bhz + i * D, bxr + i * D, bhr + i * D, bxh + i * D, bhh + i * D);
        k_build_wt2<<<(128 * 128 + 255) / 256, 256>>>(Whh + (size_t)i * D * D);
        k_csr256<<<nwblocks, 256>>>(N);
        k_wgemm<<<mtiles, 256, smem1>>>(p_sxh, p_w1h, p_w1l, N, 256, 6, 1, hi, nullptr, nullptr);
        k_csr128<<<nwblocks, 256>>>(N);
        k_wgemm<<<mtiles, 256, smem2>>>(p_Sr, p_w2h, p_w2l, N, 128, 2, 2, hi, hnext, oi);
    }
}

// round 8
// speedup vs baseline: 1.2673x; 1.2673x over previous
#include <cuda_runtime.h>
#include <cuda_bf16.h>
#include <cuda_fp16.h>
#include <mma.h>
#include <math.h>
#include <stdint.h>

using namespace nvcuda;

#define D 128
#define MAXN 50432
#define MAXE 1700000

// ---------------- scratch (device globals: allocation-free) ----------------
__device__ float g_dinv[MAXN];                 // deg -> rsqrt(deg)
__device__ int   g_cnt[MAXN];                  // in-degree histogram
__device__ int   g_off[MAXN + 1];              // CSR offsets
__device__ int   g_cur[MAXN];                  // placement cursors
__device__ int   g_tmp[MAXN];                  // scan scratch
__device__ int   g_part[64];                   // scan block partials
__device__ int2  g_srt[MAXE];                  // packed (row, norm) per edge, grouped by col
__device__ __half g_xhh[(size_t)MAXN * 256];   // [x|h] fp16 gather source
__device__ __half g_rhh[(size_t)MAXN * D];     // r*h fp16 gather source
__device__ float g_sxh[(size_t)MAXN * 256];    // [S@xin | S@h]   (GEMM1 A, fp32)
__device__ float g_P[(size_t)MAXN * 384];      // GEMM1 out: [z_pre | r_pre | xh_part]
__device__ float g_Sr[(size_t)MAXN * D];       // S @ (r*h)      (GEMM2 A, fp32)
__device__ float g_Q[(size_t)MAXN * D];        // GEMM2 out
__device__ float g_z[(size_t)MAXN * D];        // z gate
__device__ __nv_bfloat16 g_Wt1hi[384 * 256];   // GEMM1 B (n-major, split)
__device__ __nv_bfloat16 g_Wt1lo[384 * 256];
__device__ __nv_bfloat16 g_Wt2hi[128 * 128];   // GEMM2 B (n-major, split)
__device__ __nv_bfloat16 g_Wt2lo[128 * 128];

__device__ __forceinline__ float sigmoidf(float x) { return 1.0f / (1.0f + expf(-x)); }

// ---------------- degree / histogram ----------------
__global__ void k_deg_init(int n) {
    int i = blockIdx.x * blockDim.x + threadIdx.x;
    if (i < n) { g_dinv[i] = 1.0f; g_cnt[i] = 0; }
}
__global__ void k_deg_edges(const int* __restrict__ coli, const float* __restrict__ w, int E) {
    int e = blockIdx.x * blockDim.x + threadIdx.x;
    if (e < E) {
        int c = coli[e];
        atomicAdd(&g_dinv[c], w[e]);
        atomicAdd(&g_cnt[c], 1);
    }
}
__global__ void k_dinv(int n) {
    int i = blockIdx.x * blockDim.x + threadIdx.x;
    if (i < n) {
        float d = g_dinv[i];
        g_dinv[i] = (d > 0.0f) ? rsqrtf(d) : 0.0f;
    }
}

// ---------------- multi-block scan ----------------
__global__ void __launch_bounds__(1024)
k_scan1(int n) {
    __shared__ int warpsum[32];
    int i = blockIdx.x * 1024 + threadIdx.x;
    int lane = threadIdx.x & 31, wid = threadIdx.x >> 5;
    int v = (i < n) ? g_cnt[i] : 0;
    int x = v;
#pragma unroll
    for (int o = 1; o < 32; o <<= 1) {
        int t = __shfl_up_sync(~0u, x, o);
        if (lane >= o) x += t;
    }
    if (lane == 31) warpsum[wid] = x;
    __syncthreads();
    if (wid == 0) {
        int s = warpsum[lane];
#pragma unroll
        for (int o = 1; o < 32; o <<= 1) {
            int t = __shfl_up_sync(~0u, s, o);
            if (lane >= o) s += t;
        }
        warpsum[lane] = s;
    }
    __syncthreads();
    int incl = x + ((wid > 0) ? warpsum[wid - 1] : 0);
    if (i < n) g_tmp[i] = incl;
    if (threadIdx.x == 1023) g_part[blockIdx.x] = incl;
}
__global__ void k_scan2(int nb) {
    __shared__ int sm[64];
    int t = threadIdx.x;
    sm[t] = (t < nb) ? g_part[t] : 0;
    __syncthreads();
    for (int o = 1; o < 64; o <<= 1) {
        int v = (t >= o) ? sm[t - o] : 0;
        __syncthreads();
        sm[t] += v;
        __syncthreads();
    }
    g_part[t] = (t > 0) ? sm[t - 1] : 0;
}
__global__ void k_scan3(int n) {
    int i = blockIdx.x * blockDim.x + threadIdx.x;
    if (i >= n) return;
    int off = g_tmp[i] + g_part[i >> 10];
    g_off[i + 1] = off;
    g_cur[i] = off - g_cnt[i];
    if (i == 0) g_off[0] = 0;
}

// ---------------- placement scatter ----------------
__global__ void k_place(const int* __restrict__ rowi, const int* __restrict__ coli,
                        const float* __restrict__ w, int E) {
    int e = blockIdx.x * blockDim.x + threadIdx.x;
    if (e >= E) return;
    int r = rowi[e], c = coli[e];
    float nrm = w[e] * __ldg(g_dinv + r) * __ldg(g_dinv + c);
    int pos = atomicAdd(&g_cur[c], 1);
    g_srt[pos] = make_int2(r, __float_as_int(nrm));
}

// ---------------- weight build (transposed + bf16 split) ----------------
__global__ void k_build_wt1(const float* __restrict__ Wxz, const float* __restrict__ Whz,
                            const float* __restrict__ Wxr, const float* __restrict__ Whr,
                            const float* __restrict__ Wxh) {
    int idx = blockIdx.x * blockDim.x + threadIdx.x;
    if (idx >= 384 * 256) return;
    int n = idx / 256, k = idx % 256;
    int blk = n >> 7, nn = n & 127;
    float v;
    if (blk == 0)      v = (k < 128) ? Wxz[k * 128 + nn] : Whz[(k - 128) * 128 + nn];
    else if (blk == 1) v = (k < 128) ? Wxr[k * 128 + nn] : Whr[(k - 128) * 128 + nn];
    else               v = (k < 128) ? Wxh[k * 128 + nn] : 0.0f;
    __nv_bfloat16 hi = __float2bfloat16(v);
    g_Wt1hi[idx] = hi;
    g_Wt1lo[idx] = __float2bfloat16(v - __bfloat162float(hi));
}
__global__ void k_build_wt2(const float* __restrict__ Whh) {
    int idx = blockIdx.x * blockDim.x + threadIdx.x;
    if (idx >= 128 * 128) return;
    int n = idx / 128, k = idx % 128;
    float v = Whh[k * 128 + n];
    __nv_bfloat16 hi = __float2bfloat16(v);
    g_Wt2hi[idx] = hi;
    g_Wt2lo[idx] = __float2bfloat16(v - __bfloat162float(hi));
}

// ---------------- prep: pack [x|h] fp32 -> fp16 gather rows (layer 0 only) ----------------
__global__ void k_prep(const float* __restrict__ x, const float* __restrict__ h, int n) {
    int idx = blockIdx.x * blockDim.x + threadIdx.x;
    if (idx >= n * 32) return;
    int m = idx >> 5, j = idx & 31;
    const float4* src = (j < 16) ? (const float4*)x + (size_t)m * 32 + 2 * j
                                 : (const float4*)h + (size_t)m * 32 + 2 * (j - 16);
    float4 a = __ldg(src), b = __ldg(src + 1);
    __half2 h0 = __floats2half2_rn(a.x, a.y), h1 = __floats2half2_rn(a.z, a.w);
    __half2 h2 = __floats2half2_rn(b.x, b.y), h3 = __floats2half2_rn(b.z, b.w);
    uint4 o;
    o.x = *(uint32_t*)&h0; o.y = *(uint32_t*)&h1; o.z = *(uint32_t*)&h2; o.w = *(uint32_t*)&h3;
    ((uint4*)g_xhh)[(size_t)m * 32 + j] = o;
}

// ---------------- CSR gather: 256-wide fp16 -> g_sxh fp32, warp per node ----------------
__global__ void __launch_bounds__(256)
k_csr256(int n) {
    int node = (blockIdx.x * blockDim.x + threadIdx.x) >> 5;
    if (node >= n) return;
    int lane = threadIdx.x & 31;
    const uint4* src = (const uint4*)g_xhh;
    float di = __ldg(g_dinv + node);
    float s = di * di;
    float acc[8];
    {
        uint4 v = __ldg(src + (size_t)node * 32 + lane);
        float2 f0 = __half22float2(*(__half2*)&v.x), f1 = __half22float2(*(__half2*)&v.y);
        float2 f2 = __half22float2(*(__half2*)&v.z), f3 = __half22float2(*(__half2*)&v.w);
        acc[0] = s * f0.x; acc[1] = s * f0.y; acc[2] = s * f1.x; acc[3] = s * f1.y;
        acc[4] = s * f2.x; acc[5] = s * f2.y; acc[6] = s * f3.x; acc[7] = s * f3.y;
    }
    int e0 = __ldg(g_off + node), e1 = __ldg(g_off + node + 1);
#pragma unroll 8
    for (int e = e0; e < e1; e++) {
        int2 p = __ldg(g_srt + e);
        float nrm = __int_as_float(p.y);
        uint4 v = __ldg(src + (size_t)p.x * 32 + lane);
        float2 f0 = __half22float2(*(__half2*)&v.x), f1 = __half22float2(*(__half2*)&v.y);
        float2 f2 = __half22float2(*(__half2*)&v.z), f3 = __half22float2(*(__half2*)&v.w);
        acc[0] += nrm * f0.x; acc[1] += nrm * f0.y; acc[2] += nrm * f1.x; acc[3] += nrm * f1.y;
        acc[4] += nrm * f2.x; acc[5] += nrm * f2.y; acc[6] += nrm * f3.x; acc[7] += nrm * f3.y;
    }
    float4* dst = (float4*)g_sxh + (size_t)node * 64 + 2 * lane;
    dst[0] = make_float4(acc[0], acc[1], acc[2], acc[3]);
    dst[1] = make_float4(acc[4], acc[5], acc[6], acc[7]);
}

// ---------------- CSR gather: 128-wide fp16 (g_rhh -> g_Sr), warp per node ----------------
__global__ void __launch_bounds__(256)
k_csr128(int n) {
    int node = (blockIdx.x * blockDim.x + threadIdx.x) >> 5;
    if (node >= n) return;
    int lane = threadIdx.x & 31;
    const uint2* src = (const uint2*)g_rhh;
    float di = __ldg(g_dinv + node);
    float s = di * di;
    float acc[4];
    {
        uint2 v = __ldg(src + (size_t)node * 32 + lane);
        float2 f0 = __half22float2(*(__half2*)&v.x), f1 = __half22float2(*(__half2*)&v.y);
        acc[0] = s * f0.x; acc[1] = s * f0.y; acc[2] = s * f1.x; acc[3] = s * f1.y;
    }
    int e0 = __ldg(g_off + node), e1 = __ldg(g_off + node + 1);
#pragma unroll 8
    for (int e = e0; e < e1; e++) {
        int2 p = __ldg(g_srt + e);
        float nrm = __int_as_float(p.y);
        uint2 v = __ldg(src + (size_t)p.x * 32 + lane);
        float2 f0 = __half22float2(*(__half2*)&v.x), f1 = __half22float2(*(__half2*)&v.y);
        acc[0] += nrm * f0.x; acc[1] += nrm * f0.y; acc[2] += nrm * f1.x; acc[3] += nrm * f1.y;
    }
    ((float4*)g_Sr)[(size_t)node * 32 + lane] = make_float4(acc[0], acc[1], acc[2], acc[3]);
}

// ---------------- WMMA split-bf16 GEMM (A loaded once, loop over N tiles) --------
__global__ void __launch_bounds__(256, 1)
k_wgemm(const float* __restrict__ A, const __nv_bfloat16* __restrict__ Bhi,
        const __nv_bfloat16* __restrict__ Blo, float* __restrict__ C,
        int M, int K, int ldC, int ntiles) {
    extern __shared__ char smem[];
    const int tid = threadIdx.x;
    const int blockRow = blockIdx.x * 128;
    const int ldS = K + 16;

    __nv_bfloat16* Ahi = (__nv_bfloat16*)smem;
    __nv_bfloat16* Alo = Ahi + 128 * ldS;
    __nv_bfloat16* Bh  = Alo + 128 * ldS;
    __nv_bfloat16* Bl  = Bh + 64 * ldS;

    {
        const int K4 = K >> 2;
        for (int idx = tid; idx < 128 * K4; idx += 256) {
            int r = idx / K4, c = (idx % K4) * 4;
            float4 v = __ldg((const float4*)(A + (size_t)(blockRow + r) * K + c));
            __nv_bfloat16 h0 = __float2bfloat16(v.x), h1 = __float2bfloat16(v.y);
            __nv_bfloat16 h2 = __float2bfloat16(v.z), h3 = __float2bfloat16(v.w);
            __nv_bfloat16 l0 = __float2bfloat16(v.x - __bfloat162float(h0));
            __nv_bfloat16 l1 = __float2bfloat16(v.y - __bfloat162float(h1));
            __nv_bfloat16 l2 = __float2bfloat16(v.z - __bfloat162float(h2));
            __nv_bfloat16 l3 = __float2bfloat16(v.w - __bfloat162float(h3));
            uint32_t hw0 = ((uint32_t)__bfloat16_as_ushort(h1) << 16) | __bfloat16_as_ushort(h0);
            uint32_t hw1 = ((uint32_t)__bfloat16_as_ushort(h3) << 16) | __bfloat16_as_ushort(h2);
            uint32_t lw0 = ((uint32_t)__bfloat16_as_ushort(l1) << 16) | __bfloat16_as_ushort(l0);
            uint32_t lw1 = ((uint32_t)__bfloat16_as_ushort(l3) << 16) | __bfloat16_as_ushort(l2);
            *(uint2*)(Ahi + (size_t)r * ldS + c) = make_uint2(hw0, hw1);
            *(uint2*)(Alo + (size_t)r * ldS + c) = make_uint2(lw0, lw1);
        }
    }

    const int warpId = tid >> 5;
    const int wm = warpId & 3;
    const int wn = warpId >> 2;
    const int row0 = wm * 32;
    const int col0 = wn * 32;
    const int K8 = K >> 3;

    for (int nt = 0; nt < ntiles; nt++) {
        const int n0 = nt * 64;
        __syncthreads();
        for (int idx = tid; idx < 64 * K8; idx += 256) {
            int n = idx / K8, c = (idx % K8) * 8;
            uint4 vh = __ldg((const uint4*)(Bhi + (size_t)(n0 + n) * K + c));
            uint4 vl = __ldg((const uint4*)(Blo + (size_t)(n0 + n) * K + c));
            *(uint4*)(Bh + (size_t)n * ldS + c) = vh;
            *(uint4*)(Bl + (size_t)n * ldS + c) = vl;
        }
        __syncthreads();

        wmma::fragment<wmma::accumulator, 16, 16, 16, float> acc[2][2];
#pragma unroll
        for (int i = 0; i < 2; i++)
#pragma unroll
            for (int j = 0; j < 2; j++) wmma::fill_fragment(acc[i][j], 0.0f);

        for (int k0 = 0; k0 < K; k0 += 16) {
            wmma::fragment<wmma::matrix_a, 16, 16, 16, __nv_bfloat16, wmma::row_major> ah[2], al[2];
            wmma::fragment<wmma::matrix_b, 16, 16, 16, __nv_bfloat16, wmma::col_major> bh[2], bl[2];
#pragma unroll
            for (int i = 0; i < 2; i++) {
                wmma::load_matrix_sync(ah[i], Ahi + (size_t)(row0 + i * 16) * ldS + k0, ldS);
                wmma::load_matrix_sync(al[i], Alo + (size_t)(row0 + i * 16) * ldS + k0, ldS);
            }
#pragma unroll
            for (int j = 0; j < 2; j++) {
                wmma::load_matrix_sync(bh[j], Bh + (size_t)(col0 + j * 16) * ldS + k0, ldS);
                wmma::load_matrix_sync(bl[j], Bl + (size_t)(col0 + j * 16) * ldS + k0, ldS);
            }
#pragma unroll
            for (int i = 0; i < 2; i++)
#pragma unroll
                for (int j = 0; j < 2; j++) {
                    wmma::mma_sync(acc[i][j], ah[i], bh[j], acc[i][j]);
                    wmma::mma_sync(acc[i][j], ah[i], bl[j], acc[i][j]);
                    wmma::mma_sync(acc[i][j], al[i], bh[j], acc[i][j]);
                }
        }

#pragma unroll
        for (int i = 0; i < 2; i++)
#pragma unroll
            for (int j = 0; j < 2; j++) {
                float* cp = C + (size_t)(blockRow + row0 + i * 16) * ldC + n0 + col0 + j * 16;
                wmma::store_matrix_sync(cp, acc[i][j], ldC, wmma::mem_row_major);
            }
    }
}

// ---------------- gates: z fp32, rh -> fp16 gather source ----------------
__global__ void k_gate(const float* __restrict__ hi,
                       const float* __restrict__ bxz, const float* __restrict__ bhz,
                       const float* __restrict__ bxr, const float* __restrict__ bhr, int n) {
    int idx = blockIdx.x * blockDim.x + threadIdx.x;
    if (idx >= n * 32) return;
    int m = idx >> 5, j = idx & 31;
    const float4* P4 = (const float4*)g_P;
    float4 pz = P4[(size_t)m * 96 + j];
    float4 pr = P4[(size_t)m * 96 + 32 + j];
    float4 b0 = __ldg((const float4*)bxz + j);
    float4 b1 = __ldg((const float4*)bhz + j);
    float4 b2 = __ldg((const float4*)bxr + j);
    float4 b3 = __ldg((const float4*)bhr + j);
    float4 hv = __ldg((const float4*)hi + (size_t)m * 32 + j);

    float4 z, rh;
    z.x = sigmoidf(pz.x + b0.x + b1.x); z.y = sigmoidf(pz.y + b0.y + b1.y);
    z.z = sigmoidf(pz.z + b0.z + b1.z); z.w = sigmoidf(pz.w + b0.w + b1.w);
    float rx = sigmoidf(pr.x + b2.x + b3.x), ry = sigmoidf(pr.y + b2.y + b3.y);
    float rz = sigmoidf(pr.z + b2.z + b3.z), rw = sigmoidf(pr.w + b2.w + b3.w);
    rh.x = rx * hv.x; rh.y = ry * hv.y; rh.z = rz * hv.z; rh.w = rw * hv.w;

    ((float4*)g_z)[(size_t)m * 32 + j] = z;
    __half2 p0 = __floats2half2_rn(rh.x, rh.y), p1 = __floats2half2_rn(rh.z, rh.w);
    uint2 packed;
    packed.x = *(uint32_t*)&p0; packed.y = *(uint32_t*)&p1;
    ((uint2*)g_rhh)[(size_t)m * 32 + j] = packed;
}

// ---------------- final: ho; optionally pack next layer's [ho|hnext] fp16 ----------------
__global__ void k_final(const float* __restrict__ hi,
                        const float* __restrict__ bxh, const float* __restrict__ bhh,
                        const float* __restrict__ hnext,
                        float* __restrict__ out, int n) {
    int idx = blockIdx.x * blockDim.x + threadIdx.x;
    if (idx >= n * 32) return;
    int m = idx >> 5, j = idx & 31;
    float4 pxh = ((const float4*)g_P)[(size_t)m * 96 + 64 + j];
    float4 q = ((const float4*)g_Q)[(size_t)m * 32 + j];
    float4 b0 = __ldg((const float4*)bxh + j);
    float4 b1 = __ldg((const float4*)bhh + j);
    float4 zv = ((const float4*)g_z)[(size_t)m * 32 + j];
    float4 hv = __ldg((const float4*)hi + (size_t)m * 32 + j);
    float4 ho;
    float ht;
    ht = tanhf(pxh.x + q.x + b0.x + b1.x); ho.x = zv.x * hv.x + (1.0f - zv.x) * ht;
    ht = tanhf(pxh.y + q.y + b0.y + b1.y); ho.y = zv.y * hv.y + (1.0f - zv.y) * ht;
    ht = tanhf(pxh.z + q.z + b0.z + b1.z); ho.z = zv.z * hv.z + (1.0f - zv.z) * ht;
    ht = tanhf(pxh.w + q.w + b0.w + b1.w); ho.w = zv.w * hv.w + (1.0f - zv.w) * ht;
    ((float4*)out)[(size_t)m * 32 + j] = ho;
    if (hnext) {
        __half2 x0 = __floats2half2_rn(ho.x, ho.y), x1 = __floats2half2_rn(ho.z, ho.w);
        uint2 px; px.x = *(uint32_t*)&x0; px.y = *(uint32_t*)&x1;
        ((uint2*)g_xhh)[(size_t)m * 64 + j] = px;                 // x-half
        float4 hn = __ldg((const float4*)hnext + (size_t)m * 32 + j);
        __half2 n0 = __floats2half2_rn(hn.x, hn.y), n1 = __floats2half2_rn(hn.z, hn.w);
        uint2 pn; pn.x = *(uint32_t*)&n0; pn.y = *(uint32_t*)&n1;
        ((uint2*)g_xhh)[(size_t)m * 64 + 32 + j] = pn;            // h-half
    }
}

// ---------------- host ----------------
extern "C" void kernel_launch(void* const* d_in, const int* in_sizes, int n_in,
                              void* d_out, int out_size) {
    const float* x   = (const float*)d_in[0];
    const int*   ei  = (const int*)d_in[1];
    const float* ew  = (const float*)d_in[2];
    const float* h   = (const float*)d_in[3];
    const float* Wxz = (const float*)d_in[4];  const float* bxz = (const float*)d_in[5];
    const float* Whz = (const float*)d_in[6];  const float* bhz = (const float*)d_in[7];
    const float* Wxr = (const float*)d_in[8];  const float* bxr = (const float*)d_in[9];
    const float* Whr = (const float*)d_in[10]; const float* bhr = (const float*)d_in[11];
    const float* Wxh = (const float*)d_in[12]; const float* bxh = (const float*)d_in[13];
    const float* Whh = (const float*)d_in[14]; const float* bhh = (const float*)d_in[15];
    float* out = (float*)d_out;

    int N = in_sizes[0] / D;
    int E = in_sizes[2];
    int L = in_sizes[5] / D;

    const int* rowi = ei;
    const int* coli = ei + E;

    float *p_sxh, *p_P, *p_Sr, *p_Q;
    __nv_bfloat16 *p_w1h, *p_w1l, *p_w2h, *p_w2l;
    cudaGetSymbolAddress((void**)&p_sxh, g_sxh);
    cudaGetSymbolAddress((void**)&p_P,   g_P);
    cudaGetSymbolAddress((void**)&p_Sr,  g_Sr);
    cudaGetSymbolAddress((void**)&p_Q,   g_Q);
    cudaGetSymbolAddress((void**)&p_w1h, g_Wt1hi);
    cudaGetSymbolAddress((void**)&p_w1l, g_Wt1lo);
    cudaGetSymbolAddress((void**)&p_w2h, g_Wt2hi);
    cudaGetSymbolAddress((void**)&p_w2l, g_Wt2lo);

    int smem1 = 2 * (128 + 64) * (256 + 16) * 2;  // K=256
    int smem2 = 2 * (128 + 64) * (128 + 16) * 2;  // K=128
    cudaFuncSetAttribute(k_wgemm, cudaFuncAttributeMaxDynamicSharedMemorySize, smem1);

    // ---- one-time: degrees, CSR build ----
    k_deg_init<<<(N + 255) / 256, 256>>>(N);
    k_deg_edges<<<(E + 255) / 256, 256>>>(coli, ew, E);
    k_dinv<<<(N + 255) / 256, 256>>>(N);
    int nscan = (N + 1023) / 1024;
    k_scan1<<<nscan, 1024>>>(N);
    k_scan2<<<1, 64>>>(nscan);
    k_scan3<<<(N + 255) / 256, 256>>>(N);
    k_place<<<(E + 255) / 256, 256>>>(rowi, coli, ew, E);

    int nwblocks = (N * 32 + 255) / 256;  // warp per node
    int mtiles = (N + 127) / 128;

    k_prep<<<(N * 32 + 255) / 256, 256>>>(x, h, N);  // layer 0 pack only

    for (int i = 0; i < L; i++) {
        const float* hi = h + (size_t)i * N * D;
        const float* hnext = (i + 1 < L) ? h + (size_t)(i + 1) * N * D : nullptr;

        k_build_wt1<<<(384 * 256 + 255) / 256, 256>>>(Wxz + (size_t)i * D * D, Whz + (size_t)i * D * D,
                                                      Wxr + (size_t)i * D * D, Whr + (size_t)i * D * D,
                                                      Wxh + (size_t)i * D * D);
        k_build_wt2<<<(128 * 128 + 255) / 256, 256>>>(Whh + (size_t)i * D * D);
        k_csr256<<<nwblocks, 256>>>(N);
        k_wgemm<<<mtiles, 256, smem1>>>(p_sxh, p_w1h, p_w1l, p_P, N, 256, 384, 6);
        k_gate<<<(N * 32 + 255) / 256, 256>>>(hi, bxz + i * D, bhz + i * D, bxr + i * D, bhr + i * D, N);
        k_csr128<<<nwblocks, 256>>>(N);
        k_wgemm<<<mtiles, 256, smem2>>>(p_Sr, p_w2h, p_w2l, p_Q, N, 128, 128, 2);
        k_final<<<(N * 32 + 255) / 256, 256>>>(hi, bxh + i * D, bhh + i * D, hnext,
                                               out + (size_t)i * N * D, N);
    }
}

// round 9
// speedup vs baseline: 1.5118x; 1.1929x over previous
#include <cuda_runtime.h>
#include <cuda_fp16.h>
#include <mma.h>
#include <math.h>
#include <stdint.h>

using namespace nvcuda;

#define D 128
#define MAXN 50432
#define MAXE 1700000
#define LO_SCALE 1024.0f
#define INV_LO (1.0f / 1024.0f)

// ---------------- scratch (device globals: allocation-free) ----------------
__device__ float g_dinv[MAXN];                 // deg -> rsqrt(deg)
__device__ int   g_cnt[MAXN];                  // in-degree histogram
__device__ int   g_off[MAXN + 1];              // CSR offsets
__device__ int   g_cur[MAXN];                  // placement cursors
__device__ int   g_tmp[MAXN];                  // scan scratch
__device__ int   g_part[64];                   // scan block partials
__device__ int2  g_srt[MAXE];                  // packed (row, norm) per edge, grouped by col
__device__ __half g_xhh[(size_t)MAXN * 256];   // [x|h] fp16 gather source
__device__ __half g_rhh[(size_t)MAXN * D];     // r*h fp16 gather source
__device__ __half g_axh[(size_t)MAXN * 256];   // [S@x | S@h]  (GEMM1 A, fp16)
__device__ __half g_aSr[(size_t)MAXN * D];     // S@(r*h)      (GEMM2 A, fp16)
__device__ float g_P[(size_t)MAXN * 384];      // GEMM1 out: [z_pre | r_pre | xh_part]
__device__ float g_Q[(size_t)MAXN * D];        // GEMM2 out
__device__ float g_z[(size_t)MAXN * D];        // z gate
__device__ __half g_W1h[2 * 384 * 256];        // GEMM1 B hi (n-major, per layer)
__device__ __half g_W1l[2 * 384 * 256];        // GEMM1 B lo*1024
__device__ __half g_W2h[2 * 128 * 128];        // GEMM2 B hi
__device__ __half g_W2l[2 * 128 * 128];        // GEMM2 B lo*1024

__device__ __forceinline__ float sigmoidf(float x) { return 1.0f / (1.0f + expf(-x)); }

// ---------------- degree / histogram ----------------
__global__ void k_deg_init(int n) {
    int i = blockIdx.x * blockDim.x + threadIdx.x;
    if (i < n) { g_dinv[i] = 1.0f; g_cnt[i] = 0; }
}
__global__ void k_deg_edges(const int* __restrict__ coli, const float* __restrict__ w, int E) {
    int e = blockIdx.x * blockDim.x + threadIdx.x;
    if (e < E) {
        int c = coli[e];
        atomicAdd(&g_dinv[c], w[e]);
        atomicAdd(&g_cnt[c], 1);
    }
}
__global__ void k_dinv(int n) {
    int i = blockIdx.x * blockDim.x + threadIdx.x;
    if (i < n) {
        float d = g_dinv[i];
        g_dinv[i] = (d > 0.0f) ? rsqrtf(d) : 0.0f;
    }
}

// ---------------- multi-block scan ----------------
__global__ void __launch_bounds__(1024)
k_scan1(int n) {
    __shared__ int warpsum[32];
    int i = blockIdx.x * 1024 + threadIdx.x;
    int lane = threadIdx.x & 31, wid = threadIdx.x >> 5;
    int v = (i < n) ? g_cnt[i] : 0;
    int x = v;
#pragma unroll
    for (int o = 1; o < 32; o <<= 1) {
        int t = __shfl_up_sync(~0u, x, o);
        if (lane >= o) x += t;
    }
    if (lane == 31) warpsum[wid] = x;
    __syncthreads();
    if (wid == 0) {
        int s = warpsum[lane];
#pragma unroll
        for (int o = 1; o < 32; o <<= 1) {
            int t = __shfl_up_sync(~0u, s, o);
            if (lane >= o) s += t;
        }
        warpsum[lane] = s;
    }
    __syncthreads();
    int incl = x + ((wid > 0) ? warpsum[wid - 1] : 0);
    if (i < n) g_tmp[i] = incl;
    if (threadIdx.x == 1023) g_part[blockIdx.x] = incl;
}
__global__ void k_scan2(int nb) {
    __shared__ int sm[64];
    int t = threadIdx.x;
    sm[t] = (t < nb) ? g_part[t] : 0;
    __syncthreads();
    for (int o = 1; o < 64; o <<= 1) {
        int v = (t >= o) ? sm[t - o] : 0;
        __syncthreads();
        sm[t] += v;
        __syncthreads();
    }
    g_part[t] = (t > 0) ? sm[t - 1] : 0;
}
__global__ void k_scan3(int n) {
    int i = blockIdx.x * blockDim.x + threadIdx.x;
    if (i >= n) return;
    int off = g_tmp[i] + g_part[i >> 10];
    g_off[i + 1] = off;
    g_cur[i] = off - g_cnt[i];
    if (i == 0) g_off[0] = 0;
}

// ---------------- placement scatter ----------------
__global__ void k_place(const int* __restrict__ rowi, const int* __restrict__ coli,
                        const float* __restrict__ w, int E) {
    int e = blockIdx.x * blockDim.x + threadIdx.x;
    if (e >= E) return;
    int r = rowi[e], c = coli[e];
    float nrm = w[e] * __ldg(g_dinv + r) * __ldg(g_dinv + c);
    int pos = atomicAdd(&g_cur[c], 1);
    g_srt[pos] = make_int2(r, __float_as_int(nrm));
}

// ---------------- weight build: all layers, fp16 hi + scaled lo, n-major ----------------
__global__ void k_build_wt1(const float* __restrict__ Wxz, const float* __restrict__ Whz,
                            const float* __restrict__ Wxr, const float* __restrict__ Whr,
                            const float* __restrict__ Wxh, int L) {
    int idx = blockIdx.x * blockDim.x + threadIdx.x;
    if (idx >= L * 384 * 256) return;
    int layer = idx / (384 * 256);
    int rem = idx % (384 * 256);
    int n = rem / 256, k = rem % 256;
    int blk = n >> 7, nn = n & 127;
    size_t wo = (size_t)layer * D * D;
    float v;
    if (blk == 0)      v = (k < 128) ? Wxz[wo + k * 128 + nn] : Whz[wo + (k - 128) * 128 + nn];
    else if (blk == 1) v = (k < 128) ? Wxr[wo + k * 128 + nn] : Whr[wo + (k - 128) * 128 + nn];
    else               v = (k < 128) ? Wxh[wo + k * 128 + nn] : 0.0f;
    __half hi = __float2half_rn(v);
    g_W1h[idx] = hi;
    g_W1l[idx] = __float2half_rn((v - __half2float(hi)) * LO_SCALE);
}
__global__ void k_build_wt2(const float* __restrict__ Whh, int L) {
    int idx = blockIdx.x * blockDim.x + threadIdx.x;
    if (idx >= L * 128 * 128) return;
    int layer = idx / (128 * 128);
    int rem = idx % (128 * 128);
    int n = rem / 128, k = rem % 128;
    float v = Whh[(size_t)layer * D * D + k * 128 + n];
    __half hi = __float2half_rn(v);
    g_W2h[idx] = hi;
    g_W2l[idx] = __float2half_rn((v - __half2float(hi)) * LO_SCALE);
}

// ---------------- prep: pack [x|h] fp32 -> fp16 gather rows (layer 0 only) ----------------
__global__ void k_prep(const float* __restrict__ x, const float* __restrict__ h, int n) {
    int idx = blockIdx.x * blockDim.x + threadIdx.x;
    if (idx >= n * 32) return;
    int m = idx >> 5, j = idx & 31;
    const float4* src = (j < 16) ? (const float4*)x + (size_t)m * 32 + 2 * j
                                 : (const float4*)h + (size_t)m * 32 + 2 * (j - 16);
    float4 a = __ldg(src), b = __ldg(src + 1);
    __half2 h0 = __floats2half2_rn(a.x, a.y), h1 = __floats2half2_rn(a.z, a.w);
    __half2 h2 = __floats2half2_rn(b.x, b.y), h3 = __floats2half2_rn(b.z, b.w);
    uint4 o;
    o.x = *(uint32_t*)&h0; o.y = *(uint32_t*)&h1; o.z = *(uint32_t*)&h2; o.w = *(uint32_t*)&h3;
    ((uint4*)g_xhh)[(size_t)m * 32 + j] = o;
}

// ---------------- CSR gather: 256-wide fp16 -> g_axh fp16, warp per node ----------------
__global__ void __launch_bounds__(256)
k_csr256(int n) {
    int node = (blockIdx.x * blockDim.x + threadIdx.x) >> 5;
    if (node >= n) return;
    int lane = threadIdx.x & 31;
    const uint4* src = (const uint4*)g_xhh;
    float di = __ldg(g_dinv + node);
    float s = di * di;
    float acc[8];
    {
        uint4 v = __ldg(src + (size_t)node * 32 + lane);
        float2 f0 = __half22float2(*(__half2*)&v.x), f1 = __half22float2(*(__half2*)&v.y);
        float2 f2 = __half22float2(*(__half2*)&v.z), f3 = __half22float2(*(__half2*)&v.w);
        acc[0] = s * f0.x; acc[1] = s * f0.y; acc[2] = s * f1.x; acc[3] = s * f1.y;
        acc[4] = s * f2.x; acc[5] = s * f2.y; acc[6] = s * f3.x; acc[7] = s * f3.y;
    }
    int e0 = __ldg(g_off + node), e1 = __ldg(g_off + node + 1);
#pragma unroll 4
    for (int e = e0; e < e1; e++) {
        int2 p = __ldg(g_srt + e);
        float nrm = __int_as_float(p.y);
        uint4 v = __ldg(src + (size_t)p.x * 32 + lane);
        float2 f0 = __half22float2(*(__half2*)&v.x), f1 = __half22float2(*(__half2*)&v.y);
        float2 f2 = __half22float2(*(__half2*)&v.z), f3 = __half22float2(*(__half2*)&v.w);
        acc[0] += nrm * f0.x; acc[1] += nrm * f0.y; acc[2] += nrm * f1.x; acc[3] += nrm * f1.y;
        acc[4] += nrm * f2.x; acc[5] += nrm * f2.y; acc[6] += nrm * f3.x; acc[7] += nrm * f3.y;
    }
    __half2 o0 = __floats2half2_rn(acc[0], acc[1]), o1 = __floats2half2_rn(acc[2], acc[3]);
    __half2 o2 = __floats2half2_rn(acc[4], acc[5]), o3 = __floats2half2_rn(acc[6], acc[7]);
    uint4 o;
    o.x = *(uint32_t*)&o0; o.y = *(uint32_t*)&o1; o.z = *(uint32_t*)&o2; o.w = *(uint32_t*)&o3;
    ((uint4*)g_axh)[(size_t)node * 32 + lane] = o;
}

// ---------------- CSR gather: 128-wide fp16 (g_rhh -> g_aSr fp16), warp per node -------
__global__ void __launch_bounds__(256)
k_csr128(int n) {
    int node = (blockIdx.x * blockDim.x + threadIdx.x) >> 5;
    if (node >= n) return;
    int lane = threadIdx.x & 31;
    const uint2* src = (const uint2*)g_rhh;
    float di = __ldg(g_dinv + node);
    float s = di * di;
    float acc[4];
    {
        uint2 v = __ldg(src + (size_t)node * 32 + lane);
        float2 f0 = __half22float2(*(__half2*)&v.x), f1 = __half22float2(*(__half2*)&v.y);
        acc[0] = s * f0.x; acc[1] = s * f0.y; acc[2] = s * f1.x; acc[3] = s * f1.y;
    }
    int e0 = __ldg(g_off + node), e1 = __ldg(g_off + node + 1);
#pragma unroll 4
    for (int e = e0; e < e1; e++) {
        int2 p = __ldg(g_srt + e);
        float nrm = __int_as_float(p.y);
        uint2 v = __ldg(src + (size_t)p.x * 32 + lane);
        float2 f0 = __half22float2(*(__half2*)&v.x), f1 = __half22float2(*(__half2*)&v.y);
        acc[0] += nrm * f0.x; acc[1] += nrm * f0.y; acc[2] += nrm * f1.x; acc[3] += nrm * f1.y;
    }
    __half2 o0 = __floats2half2_rn(acc[0], acc[1]), o1 = __floats2half2_rn(acc[2], acc[3]);
    uint2 o;
    o.x = *(uint32_t*)&o0; o.y = *(uint32_t*)&o1;
    ((uint2*)g_aSr)[(size_t)node * 32 + lane] = o;
}

// ---------------- WMMA fp16 GEMM: A fp16, W split hi + lo*1024, 2 passes ----------------
// C = A @ (Whi + Wlo/1024)^T, fp32 accumulate in two fragments, recombined at store.
__global__ void __launch_bounds__(256)
k_wgemm(const __half* __restrict__ A, const __half* __restrict__ Bhi,
        const __half* __restrict__ Blo, float* __restrict__ C,
        int M, int K, int ldC, int ntiles) {
    extern __shared__ char smem[];
    const int tid = threadIdx.x;
    const int blockRow = blockIdx.x * 128;
    const int ldS = K + 16;

    __half* As = (__half*)smem;               // [128][ldS]
    __half* Bh = As + 128 * ldS;              // [64][ldS]
    __half* Bl = Bh + 64 * ldS;

    // ---- copy A fp16 into padded SMEM (once) ----
    {
        const int K8 = K >> 3;
        for (int idx = tid; idx < 128 * K8; idx += 256) {
            int r = idx / K8, c = (idx % K8) * 8;
            uint4 v = __ldg((const uint4*)(A + (size_t)(blockRow + r) * K + c));
            *(uint4*)(As + (size_t)r * ldS + c) = v;
        }
    }

    const int warpId = tid >> 5;
    const int wm = warpId & 3;
    const int wn = warpId >> 2;
    const int row0 = wm * 32;
    const int col0 = wn * 32;
    const int K8 = K >> 3;

    for (int nt = 0; nt < ntiles; nt++) {
        const int n0 = nt * 64;
        __syncthreads();
        for (int idx = tid; idx < 64 * K8; idx += 256) {
            int n = idx / K8, c = (idx % K8) * 8;
            uint4 vh = __ldg((const uint4*)(Bhi + (size_t)(n0 + n) * K + c));
            uint4 vl = __ldg((const uint4*)(Blo + (size_t)(n0 + n) * K + c));
            *(uint4*)(Bh + (size_t)n * ldS + c) = vh;
            *(uint4*)(Bl + (size_t)n * ldS + c) = vl;
        }
        __syncthreads();

        wmma::fragment<wmma::accumulator, 16, 16, 16, float> acch[2][2], accl[2][2];
#pragma unroll
        for (int i = 0; i < 2; i++)
#pragma unroll
            for (int j = 0; j < 2; j++) {
                wmma::fill_fragment(acch[i][j], 0.0f);
                wmma::fill_fragment(accl[i][j], 0.0f);
            }

        for (int k0 = 0; k0 < K; k0 += 16) {
            wmma::fragment<wmma::matrix_a, 16, 16, 16, __half, wmma::row_major> a[2];
            wmma::fragment<wmma::matrix_b, 16, 16, 16, __half, wmma::col_major> bh[2], bl[2];
#pragma unroll
            for (int i = 0; i < 2; i++)
                wmma::load_matrix_sync(a[i], As + (size_t)(row0 + i * 16) * ldS + k0, ldS);
#pragma unroll
            for (int j = 0; j < 2; j++) {
                wmma::load_matrix_sync(bh[j], Bh + (size_t)(col0 + j * 16) * ldS + k0, ldS);
                wmma::load_matrix_sync(bl[j], Bl + (size_t)(col0 + j * 16) * ldS + k0, ldS);
            }
#pragma unroll
            for (int i = 0; i < 2; i++)
#pragma unroll
                for (int j = 0; j < 2; j++) {
                    wmma::mma_sync(acch[i][j], a[i], bh[j], acch[i][j]);
                    wmma::mma_sync(accl[i][j], a[i], bl[j], accl[i][j]);
                }
        }

#pragma unroll
        for (int i = 0; i < 2; i++)
#pragma unroll
            for (int j = 0; j < 2; j++) {
#pragma unroll
                for (int t = 0; t < acch[i][j].num_elements; t++)
                    acch[i][j].x[t] += accl[i][j].x[t] * INV_LO;
                float* cp = C + (size_t)(blockRow + row0 + i * 16) * ldC + n0 + col0 + j * 16;
                wmma::store_matrix_sync(cp, acch[i][j], ldC, wmma::mem_row_major);
            }
    }
}

// ---------------- gates: z fp32, rh -> fp16 gather source ----------------
__global__ void k_gate(const float* __restrict__ hi,
                       const float* __restrict__ bxz, const float* __restrict__ bhz,
                       const float* __restrict__ bxr, const float* __restrict__ bhr, int n) {
    int idx = blockIdx.x * blockDim.x + threadIdx.x;
    if (idx >= n * 32) return;
    int m = idx >> 5, j = idx & 31;
    const float4* P4 = (const float4*)g_P;
    float4 pz = P4[(size_t)m * 96 + j];
    float4 pr = P4[(size_t)m * 96 + 32 + j];
    float4 b0 = __ldg((const float4*)bxz + j);
    float4 b1 = __ldg((const float4*)bhz + j);
    float4 b2 = __ldg((const float4*)bxr + j);
    float4 b3 = __ldg((const float4*)bhr + j);
    float4 hv = __ldg((const float4*)hi + (size_t)m * 32 + j);

    float4 z, rh;
    z.x = sigmoidf(pz.x + b0.x + b1.x); z.y = sigmoidf(pz.y + b0.y + b1.y);
    z.z = sigmoidf(pz.z + b0.z + b1.z); z.w = sigmoidf(pz.w + b0.w + b1.w);
    float rx = sigmoidf(pr.x + b2.x + b3.x), ry = sigmoidf(pr.y + b2.y + b3.y);
    float rz = sigmoidf(pr.z + b2.z + b3.z), rw = sigmoidf(pr.w + b2.w + b3.w);
    rh.x = rx * hv.x; rh.y = ry * hv.y; rh.z = rz * hv.z; rh.w = rw * hv.w;

    ((float4*)g_z)[(size_t)m * 32 + j] = z;
    __half2 p0 = __floats2half2_rn(rh.x, rh.y), p1 = __floats2half2_rn(rh.z, rh.w);
    uint2 packed;
    packed.x = *(uint32_t*)&p0; packed.y = *(uint32_t*)&p1;
    ((uint2*)g_rhh)[(size_t)m * 32 + j] = packed;
}

// ---------------- final: ho; optionally pack next layer's [ho|hnext] fp16 ----------------
__global__ void k_final(const float* __restrict__ hi,
                        const float* __restrict__ bxh, const float* __restrict__ bhh,
                        const float* __restrict__ hnext,
                        float* __restrict__ out, int n) {
    int idx = blockIdx.x * blockDim.x + threadIdx.x;
    if (idx >= n * 32) return;
    int m = idx >> 5, j = idx & 31;
    float4 pxh = ((const float4*)g_P)[(size_t)m * 96 + 64 + j];
    float4 q = ((const float4*)g_Q)[(size_t)m * 32 + j];
    float4 b0 = __ldg((const float4*)bxh + j);
    float4 b1 = __ldg((const float4*)bhh + j);
    float4 zv = ((const float4*)g_z)[(size_t)m * 32 + j];
    float4 hv = __ldg((const float4*)hi + (size_t)m * 32 + j);
    float4 ho;
    float ht;
    ht = tanhf(pxh.x + q.x + b0.x + b1.x); ho.x = zv.x * hv.x + (1.0f - zv.x) * ht;
    ht = tanhf(pxh.y + q.y + b0.y + b1.y); ho.y = zv.y * hv.y + (1.0f - zv.y) * ht;
    ht = tanhf(pxh.z + q.z + b0.z + b1.z); ho.z = zv.z * hv.z + (1.0f - zv.z) * ht;
    ht = tanhf(pxh.w + q.w + b0.w + b1.w); ho.w = zv.w * hv.w + (1.0f - zv.w) * ht;
    ((float4*)out)[(size_t)m * 32 + j] = ho;
    if (hnext) {
        __half2 x0 = __floats2half2_rn(ho.x, ho.y), x1 = __floats2half2_rn(ho.z, ho.w);
        uint2 px; px.x = *(uint32_t*)&x0; px.y = *(uint32_t*)&x1;
        ((uint2*)g_xhh)[(size_t)m * 64 + j] = px;                 // x-half
        float4 hn = __ldg((const float4*)hnext + (size_t)m * 32 + j);
        __half2 n0 = __floats2half2_rn(hn.x, hn.y), n1 = __floats2half2_rn(hn.z, hn.w);
        uint2 pn; pn.x = *(uint32_t*)&n0; pn.y = *(uint32_t*)&n1;
        ((uint2*)g_xhh)[(size_t)m * 64 + 32 + j] = pn;            // h-half
    }
}

// ---------------- host ----------------
extern "C" void kernel_launch(void* const* d_in, const int* in_sizes, int n_in,
                              void* d_out, int out_size) {
    const float* x   = (const float*)d_in[0];
    const int*   ei  = (const int*)d_in[1];
    const float* ew  = (const float*)d_in[2];
    const float* h   = (const float*)d_in[3];
    const float* Wxz = (const float*)d_in[4];  const float* bxz = (const float*)d_in[5];
    const float* Whz = (const float*)d_in[6];  const float* bhz = (const float*)d_in[7];
    const float* Wxr = (const float*)d_in[8];  const float* bxr = (const float*)d_in[9];
    const float* Whr = (const float*)d_in[10]; const float* bhr = (const float*)d_in[11];
    const float* Wxh = (const float*)d_in[12]; const float* bxh = (const float*)d_in[13];
    const float* Whh = (const float*)d_in[14]; const float* bhh = (const float*)d_in[15];
    float* out = (float*)d_out;

    int N = in_sizes[0] / D;
    int E = in_sizes[2];
    int L = in_sizes[5] / D;

    const int* rowi = ei;
    const int* coli = ei + E;

    float *p_P, *p_Q;
    __half *p_axh, *p_aSr, *p_w1h, *p_w1l, *p_w2h, *p_w2l;
    cudaGetSymbolAddress((void**)&p_axh, g_axh);
    cudaGetSymbolAddress((void**)&p_aSr, g_aSr);
    cudaGetSymbolAddress((void**)&p_P,   g_P);
    cudaGetSymbolAddress((void**)&p_Q,   g_Q);
    cudaGetSymbolAddress((void**)&p_w1h, g_W1h);
    cudaGetSymbolAddress((void**)&p_w1l, g_W1l);
    cudaGetSymbolAddress((void**)&p_w2h, g_W2h);
    cudaGetSymbolAddress((void**)&p_w2l, g_W2l);

    int smem1 = (128 + 64 + 64) * (256 + 16) * 2;  // K=256: 139,264 B
    int smem2 = (128 + 64 + 64) * (128 + 16) * 2;  // K=128: 73,728 B
    cudaFuncSetAttribute(k_wgemm, cudaFuncAttributeMaxDynamicSharedMemorySize, smem1);

    // ---- one-time: weight split (all layers), degrees, CSR build ----
    k_build_wt1<<<(L * 384 * 256 + 255) / 256, 256>>>(Wxz, Whz, Wxr, Whr, Wxh, L);
    k_build_wt2<<<(L * 128 * 128 + 255) / 256, 256>>>(Whh, L);
    k_deg_init<<<(N + 255) / 256, 256>>>(N);
    k_deg_edges<<<(E + 255) / 256, 256>>>(coli, ew, E);
    k_dinv<<<(N + 255) / 256, 256>>>(N);
    int nscan = (N + 1023) / 1024;
    k_scan1<<<nscan, 1024>>>(N);
    k_scan2<<<1, 64>>>(nscan);
    k_scan3<<<(N + 255) / 256, 256>>>(N);
    k_place<<<(E + 255) / 256, 256>>>(rowi, coli, ew, E);

    int nwblocks = (N * 32 + 255) / 256;  // warp per node
    int mtiles = (N + 127) / 128;

    k_prep<<<(N * 32 + 255) / 256, 256>>>(x, h, N);  // layer 0 pack only

    for (int i = 0; i < L; i++) {
        const float* hi = h + (size_t)i * N * D;
        const float* hnext = (i + 1 < L) ? h + (size_t)(i + 1) * N * D : nullptr;

        k_csr256<<<nwblocks, 256>>>(N);
        k_wgemm<<<mtiles, 256, smem1>>>(p_axh, p_w1h + (size_t)i * 384 * 256,
                                        p_w1l + (size_t)i * 384 * 256, p_P, N, 256, 384, 6);
        k_gate<<<(N * 32 + 255) / 256, 256>>>(hi, bxz + i * D, bhz + i * D, bxr + i * D, bhr + i * D, N);
        k_csr128<<<nwblocks, 256>>>(N);
        k_wgemm<<<mtiles, 256, smem2>>>(p_aSr, p_w2h + (size_t)i * 128 * 128,
                                        p_w2l + (size_t)i * 128 * 128, p_Q, N, 128, 128, 2);
        k_final<<<(N * 32 + 255) / 256, 256>>>(hi, bxh + i * D, bhh + i * D, hnext,
                                               out + (size_t)i * N * D, N);
    }
}